// round 7
// baseline (speedup 1.0000x reference)
#include <cuda_runtime.h>
#include <cstdint>
#include <cstddef>

#define NN     50000
#define HID    64
#define EMAX   800000
#define IN_DIM 512

// ---------------------------------------------------------------------------
// Scratch (__device__ globals; no allocation allowed)
// ---------------------------------------------------------------------------
__device__ __align__(256) float g_dinv[NN];
__device__ int   g_cnt[NN];
__device__ int   g_rowptr[NN + 1];
__device__ int   g_cursor[NN];
__device__ int   g_col[EMAX];
__device__ __align__(256) float g_bufA[NN * HID];
__device__ __align__(256) float g_bufB[NN * HID];

// ---------------------------------------------------------------------------
// CSR build kernels
// ---------------------------------------------------------------------------
__global__ void k_zero(int* cnt, int n) {
    int i = blockIdx.x * blockDim.x + threadIdx.x;
    if (i < n) cnt[i] = 0;
}

__global__ void k_count(const int* __restrict__ dst, int* cnt, int E) {
    int stride = gridDim.x * blockDim.x;
    for (int e = blockIdx.x * blockDim.x + threadIdx.x; e < E; e += stride)
        atomicAdd(&cnt[dst[e]], 1);
}

// single block scan: cnt -> rowptr/cursor, dinv = rsqrt(cnt+1)
__global__ void __launch_bounds__(1024)
k_scan(const int* __restrict__ cnt, int* rowptr, int* cursor,
       float* dinv, int n) {
    const int T = 1024;
    const int t = threadIdx.x;
    const int chunk = (n + T - 1) / T;
    const int beg = t * chunk;
    const int end = min(beg + chunk, n);

    int s = 0;
    for (int i = beg; i < end; i++) s += cnt[i];

    __shared__ int wsum[32];
    int lane = t & 31, wid = t >> 5;
    int v = s;
#pragma unroll
    for (int d = 1; d < 32; d <<= 1) {
        int u = __shfl_up_sync(0xffffffffu, v, d);
        if (lane >= d) v += u;
    }
    if (lane == 31) wsum[wid] = v;
    __syncthreads();
    if (wid == 0) {
        int w = wsum[lane];
#pragma unroll
        for (int d = 1; d < 32; d <<= 1) {
            int u = __shfl_up_sync(0xffffffffu, w, d);
            if (lane >= d) w += u;
        }
        wsum[lane] = w;
    }
    __syncthreads();
    int excl = v - s + (wid > 0 ? wsum[wid - 1] : 0);

    int run = excl;
    for (int i = beg; i < end; i++) {
        rowptr[i] = run;
        cursor[i] = run;
        dinv[i]   = rsqrtf((float)(cnt[i] + 1));
        run += cnt[i];
    }
    if (end == n && beg < n) rowptr[n] = run;
}

__global__ void k_fill(const int* __restrict__ src, const int* __restrict__ dst,
                       int* cursor, int* col, int E) {
    int stride = gridDim.x * blockDim.x;
    for (int e = blockIdx.x * blockDim.x + threadIdx.x; e < E; e += stride) {
        int d = dst[e];
        int pos = atomicAdd(&cursor[d], 1);
        col[pos] = src[e];
    }
}

// ---------------------------------------------------------------------------
// tf32 tensor-core GEMM, cp.async 2-stage, BK=16, STATIC smem (29.7KB).
//   h = X @ W (unscaled).
// BM=128, BN=64(full). 256 threads = 8 warps (4M x 2N), warp tile 32x32.
// ---------------------------------------------------------------------------
#define BM 128
#define BKG 16
#define PA 20   // A row stride (floats): conflict-free fragment LDS
#define PB 72   // B row stride (floats): conflict-free fragment LDS

__device__ __forceinline__ uint32_t cvt_tf32(float x) {
    uint32_t r;
    asm("cvt.rna.tf32.f32 %0, %1;" : "=r"(r) : "f"(x));
    return r;
}

template <int K>
__global__ void __launch_bounds__(256)
k_gemm(const float* __restrict__ X, const float* __restrict__ W,
       float* __restrict__ h, int M) {
    __shared__ float as[2 * BM * PA];
    __shared__ float ws[2 * BKG * PB];

    const int t    = threadIdx.x;
    const int m0   = blockIdx.x * BM;
    const int lane = t & 31;
    const int wid  = t >> 5;
    const int wm   = wid >> 1;
    const int wn   = wid & 1;
    const int g    = lane >> 2;
    const int tig  = lane & 3;

    float c[2][4][4];
#pragma unroll
    for (int mt = 0; mt < 2; mt++)
#pragma unroll
        for (int nt = 0; nt < 4; nt++)
#pragma unroll
            for (int i = 0; i < 4; i++) c[mt][nt][i] = 0.0f;

    // A tile 128x16 = 512 float4 (2/thread); B tile 16x64 = 256 float4 (1/thread)
    auto load_stage = [&](int buf, int k0) {
        float* asb = as + buf * BM * PA;
        float* wsb = ws + buf * BKG * PB;
#pragma unroll
        for (int i = 0; i < 2; i++) {
            int G = i * 256 + t;
            int row = G >> 2, gg = G & 3;
            bool ok = (m0 + row) < M;
            const float* gp = ok ? (X + (size_t)(m0 + row) * K + k0 + gg * 4) : X;
            uint32_t sa = (uint32_t)__cvta_generic_to_shared(asb + row * PA + gg * 4);
            int sz = ok ? 16 : 0;
            asm volatile("cp.async.cg.shared.global [%0], [%1], 16, %2;\n"
                         :: "r"(sa), "l"(gp), "r"(sz));
        }
        {
            int kr = t >> 4, gn = t & 15;
            const float* gp = W + (size_t)(k0 + kr) * 64 + gn * 4;
            uint32_t sa = (uint32_t)__cvta_generic_to_shared(wsb + kr * PB + gn * 4);
            asm volatile("cp.async.cg.shared.global [%0], [%1], 16;\n"
                         :: "r"(sa), "l"(gp));
        }
    };

    load_stage(0, 0);
    asm volatile("cp.async.commit_group;\n");

    const int NIT = K / BKG;
    for (int it = 0; it < NIT; it++) {
        if (it + 1 < NIT) load_stage((it + 1) & 1, (it + 1) * BKG);
        asm volatile("cp.async.commit_group;\n");
        asm volatile("cp.async.wait_group 1;\n");
        __syncthreads();

        const float* asb = as + (it & 1) * BM * PA;
        const float* wsb = ws + (it & 1) * BKG * PB;

#pragma unroll
        for (int ks = 0; ks < BKG; ks += 8) {
            uint32_t a[2][4], b[4][2];
#pragma unroll
            for (int mt = 0; mt < 2; mt++) {
                int r = wm * 32 + mt * 16 + g;
                a[mt][0] = cvt_tf32(asb[r * PA + ks + tig]);
                a[mt][1] = cvt_tf32(asb[(r + 8) * PA + ks + tig]);
                a[mt][2] = cvt_tf32(asb[r * PA + ks + tig + 4]);
                a[mt][3] = cvt_tf32(asb[(r + 8) * PA + ks + tig + 4]);
            }
#pragma unroll
            for (int nt = 0; nt < 4; nt++) {
                int n = wn * 32 + nt * 8 + g;
                b[nt][0] = cvt_tf32(wsb[(ks + tig) * PB + n]);
                b[nt][1] = cvt_tf32(wsb[(ks + tig + 4) * PB + n]);
            }
#pragma unroll
            for (int mt = 0; mt < 2; mt++)
#pragma unroll
                for (int nt = 0; nt < 4; nt++) {
                    asm volatile(
                        "mma.sync.aligned.m16n8k8.row.col.f32.tf32.tf32.f32 "
                        "{%0,%1,%2,%3}, {%4,%5,%6,%7}, {%8,%9}, {%0,%1,%2,%3};"
                        : "+f"(c[mt][nt][0]), "+f"(c[mt][nt][1]),
                          "+f"(c[mt][nt][2]), "+f"(c[mt][nt][3])
                        : "r"(a[mt][0]), "r"(a[mt][1]), "r"(a[mt][2]), "r"(a[mt][3]),
                          "r"(b[nt][0]), "r"(b[nt][1]));
                }
        }
        __syncthreads();
    }

    // --- epilogue: h = acc (unscaled)
#pragma unroll
    for (int mt = 0; mt < 2; mt++) {
        int rbase = m0 + wm * 32 + mt * 16 + g;
#pragma unroll
        for (int half = 0; half < 2; half++) {
            int row = rbase + half * 8;
            if (row < M) {
#pragma unroll
                for (int nt = 0; nt < 4; nt++) {
                    float2 v;
                    v.x = c[mt][nt][half * 2 + 0];
                    v.y = c[mt][nt][half * 2 + 1];
                    *(float2*)(h + (size_t)row * 64 + wn * 32 + nt * 8 + 2 * tig) = v;
                }
            }
        }
    }
}

// ---------------------------------------------------------------------------
// Fused aggregate (warp per node, unscaled h input):
//   out[i] = act(dinv[i] * (h[i]*dinv[i] + sum_e h[col[e]]*dinv[col[e]]) + b)
// 16-edge chunks: 32 gathers + 16 dinv loads in flight per warp.
// ---------------------------------------------------------------------------
template <bool RELU>
__global__ void __launch_bounds__(256)
k_agg(const int* __restrict__ rowptr, const int* __restrict__ col,
      const float* __restrict__ h, const float* __restrict__ dinv,
      const float* __restrict__ bias, float* __restrict__ out, int n) {
    int w = (blockIdx.x * blockDim.x + threadIdx.x) >> 5;
    int lane = threadIdx.x & 31;
    if (w >= n) return;

    float di = __ldg(&dinv[w]);
    const float* hrow = h + (size_t)w * 64;
    float a0 = __ldg(&hrow[lane]) * di;          // self-loop term
    float a1 = __ldg(&hrow[lane + 32]) * di;

    int beg = __ldg(&rowptr[w]);
    int end = __ldg(&rowptr[w + 1]);

    for (int e0 = beg; e0 < end; e0 += 16) {
        int idx = e0 + (lane & 15);
        int cs = (idx < end) ? __ldg(&col[idx]) : -1;
#pragma unroll
        for (int j = 0; j < 16; j++) {
            int s = __shfl_sync(0xffffffffu, cs, j);
            if (s >= 0) {
                float ds = __ldg(&dinv[s]);
                const float* hr = h + (size_t)s * 64;
                a0 = fmaf(__ldg(&hr[lane]),      ds, a0);
                a1 = fmaf(__ldg(&hr[lane + 32]), ds, a1);
            }
        }
    }

    float v0 = di * a0 + __ldg(&bias[lane]);
    float v1 = di * a1 + __ldg(&bias[lane + 32]);
    if (RELU) { v0 = fmaxf(v0, 0.0f); v1 = fmaxf(v1, 0.0f); }
    out[(size_t)w * 64 + lane]      = v0;
    out[(size_t)w * 64 + lane + 32] = v1;
}

// ---------------------------------------------------------------------------
// Launch (plain kernel launches only; no memset, no attributes, no guards)
// ---------------------------------------------------------------------------
extern "C" void kernel_launch(void* const* d_in, const int* in_sizes, int n_in,
                              void* d_out, int out_size) {
    const float* x  = (const float*)d_in[0];
    const int*   ei = (const int*)d_in[1];
    const float* W1 = (const float*)d_in[2];
    const float* b1 = (const float*)d_in[3];
    const float* W2 = (const float*)d_in[4];
    const float* b2 = (const float*)d_in[5];

    const int E = in_sizes[1] / 2;
    const int M = out_size / HID;
    const int* src = ei;
    const int* dst = ei + E;

    float *dinv, *bufA, *bufB;
    int *cnt, *rowptr, *cursor, *col;
    cudaGetSymbolAddress((void**)&dinv,   g_dinv);
    cudaGetSymbolAddress((void**)&cnt,    g_cnt);
    cudaGetSymbolAddress((void**)&rowptr, g_rowptr);
    cudaGetSymbolAddress((void**)&cursor, g_cursor);
    cudaGetSymbolAddress((void**)&col,    g_col);
    cudaGetSymbolAddress((void**)&bufA,   g_bufA);
    cudaGetSymbolAddress((void**)&bufB,   g_bufB);
    float* out = (float*)d_out;

    const int gblk = (M + BM - 1) / BM;
    const int ablk = (M * 32 + 255) / 256;

    // 1. CSR prefix: zero, count, scan
    k_zero<<<(M + 255) / 256, 256>>>(cnt, M);
    k_count<<<592, 256>>>(dst, cnt, E);
    k_scan<<<1, 1024>>>(cnt, rowptr, cursor, dinv, M);

    // 2. GEMM1 (launch #4 -> profiled): h1 = x@W1 (unscaled) -> bufA
    k_gemm<IN_DIM><<<gblk, 256>>>(x, W1, bufA, M);

    // 3. CSR fill -> col
    k_fill<<<592, 256>>>(src, dst, cursor, col, E);

    // 4. agg1 (+bias1, ReLU) -> bufB
    k_agg<true><<<ablk, 256>>>(rowptr, col, bufA, dinv, b1, bufB, M);

    // 5. GEMM2: h2 = bufB@W2 -> bufA ; agg2 (+bias2) -> out
    k_gemm<HID><<<gblk, 256>>>(bufB, W2, bufA, M);
    k_agg<false><<<ablk, 256>>>(rowptr, col, bufA, dinv, b2, out, M);
}

// round 8
// speedup vs baseline: 1.6660x; 1.6660x over previous
#include <cuda_runtime.h>
#include <cstdint>
#include <cstddef>

#define NN     50000
#define HID    64
#define EMAX   800000
#define IN_DIM 512
#define SCAN_B 256

// ---------------------------------------------------------------------------
// Scratch (__device__ globals; no allocation allowed)
// ---------------------------------------------------------------------------
__device__ __align__(256) float g_dinv[NN];
__device__ int   g_cnt[NN];
__device__ int   g_rowptr[NN + 1];
__device__ int   g_cursor[NN];
__device__ int   g_col[EMAX];
__device__ int   g_bsum[(NN + SCAN_B - 1) / SCAN_B];
__device__ int   g_boff[(NN + SCAN_B - 1) / SCAN_B];
__device__ __align__(256) float g_bufA[NN * HID];
__device__ __align__(256) float g_bufB[NN * HID];

// ---------------------------------------------------------------------------
// CSR build
// ---------------------------------------------------------------------------
__global__ void k_zero(int* cnt, int n) {
    int i = blockIdx.x * blockDim.x + threadIdx.x;
    if (i < n) cnt[i] = 0;
}

__global__ void k_count(const int* __restrict__ dst, int* cnt, int E) {
    int stride = gridDim.x * blockDim.x;
    for (int e = blockIdx.x * blockDim.x + threadIdx.x; e < E; e += stride)
        atomicAdd(&cnt[dst[e]], 1);
}

// S1: per-block sums of cnt (coalesced)
__global__ void __launch_bounds__(SCAN_B)
k_s1(const int* __restrict__ cnt, int* bsum, int n) {
    int i = blockIdx.x * SCAN_B + threadIdx.x;
    int v = (i < n) ? cnt[i] : 0;
#pragma unroll
    for (int d = 16; d > 0; d >>= 1) v += __shfl_down_sync(0xffffffffu, v, d);
    __shared__ int ws[8];
    int lane = threadIdx.x & 31, wid = threadIdx.x >> 5;
    if (lane == 0) ws[wid] = v;
    __syncthreads();
    if (wid == 0) {
        int s = (lane < 8) ? ws[lane] : 0;
#pragma unroll
        for (int d = 4; d > 0; d >>= 1) s += __shfl_down_sync(0xffffffffu, s, d);
        if (lane == 0) bsum[blockIdx.x] = s;
    }
}

// S2: single small block scans the per-block sums -> offsets; writes rowptr[n]
__global__ void __launch_bounds__(SCAN_B)
k_s2(const int* __restrict__ bsum, int* boff, int* rowptr, int nb, int n) {
    int t = threadIdx.x;
    int v = (t < nb) ? bsum[t] : 0;
    int lane = t & 31, wid = t >> 5;
    int inc = v;
#pragma unroll
    for (int d = 1; d < 32; d <<= 1) {
        int u = __shfl_up_sync(0xffffffffu, inc, d);
        if (lane >= d) inc += u;
    }
    __shared__ int ws[8];
    if (lane == 31) ws[wid] = inc;
    __syncthreads();
    if (wid == 0 && lane < 8) {
        int w = ws[lane];
#pragma unroll
        for (int d = 1; d < 8; d <<= 1) {
            int u = __shfl_up_sync(0xffu, w, d);
            if (lane >= d) w += u;
        }
        ws[lane] = w;
    }
    __syncthreads();
    int incl = inc + (wid > 0 ? ws[wid - 1] : 0);
    int excl = incl - v;
    if (t < nb) boff[t] = excl;
    if (t == nb - 1) rowptr[n] = incl;
}

// S3: block-local exclusive scan + offset; writes rowptr/cursor/dinv (coalesced)
__global__ void __launch_bounds__(SCAN_B)
k_s3(const int* __restrict__ cnt, const int* __restrict__ boff,
     int* rowptr, int* cursor, float* dinv, int n) {
    int t = threadIdx.x;
    int i = blockIdx.x * SCAN_B + t;
    int c = (i < n) ? cnt[i] : 0;
    int lane = t & 31, wid = t >> 5;
    int inc = c;
#pragma unroll
    for (int d = 1; d < 32; d <<= 1) {
        int u = __shfl_up_sync(0xffffffffu, inc, d);
        if (lane >= d) inc += u;
    }
    __shared__ int ws[8];
    if (lane == 31) ws[wid] = inc;
    __syncthreads();
    if (wid == 0 && lane < 8) {
        int w = ws[lane];
#pragma unroll
        for (int d = 1; d < 8; d <<= 1) {
            int u = __shfl_up_sync(0xffu, w, d);
            if (lane >= d) w += u;
        }
        ws[lane] = w;
    }
    __syncthreads();
    int excl = inc - c + (wid > 0 ? ws[wid - 1] : 0) + boff[blockIdx.x];
    if (i < n) {
        rowptr[i] = excl;
        cursor[i] = excl;
        dinv[i]   = rsqrtf((float)(c + 1));
    }
}

__global__ void k_fill(const int* __restrict__ src, const int* __restrict__ dst,
                       int* cursor, int* col, int E) {
    int stride = gridDim.x * blockDim.x;
    for (int e = blockIdx.x * blockDim.x + threadIdx.x; e < E; e += stride) {
        int d = dst[e];
        int pos = atomicAdd(&cursor[d], 1);
        col[pos] = src[e];
    }
}

// ---------------------------------------------------------------------------
// tf32 tensor-core GEMM, cp.async 2-stage, BK=16, static smem (29.7KB).
//   h = X @ W (unscaled).
// ---------------------------------------------------------------------------
#define BM 128
#define BKG 16
#define PA 20
#define PB 72

__device__ __forceinline__ uint32_t cvt_tf32(float x) {
    uint32_t r;
    asm("cvt.rna.tf32.f32 %0, %1;" : "=r"(r) : "f"(x));
    return r;
}

template <int K>
__global__ void __launch_bounds__(256)
k_gemm(const float* __restrict__ X, const float* __restrict__ W,
       float* __restrict__ h, int M) {
    __shared__ float as[2 * BM * PA];
    __shared__ float ws[2 * BKG * PB];

    const int t    = threadIdx.x;
    const int m0   = blockIdx.x * BM;
    const int lane = t & 31;
    const int wid  = t >> 5;
    const int wm   = wid >> 1;
    const int wn   = wid & 1;
    const int g    = lane >> 2;
    const int tig  = lane & 3;

    float c[2][4][4];
#pragma unroll
    for (int mt = 0; mt < 2; mt++)
#pragma unroll
        for (int nt = 0; nt < 4; nt++)
#pragma unroll
            for (int i = 0; i < 4; i++) c[mt][nt][i] = 0.0f;

    auto load_stage = [&](int buf, int k0) {
        float* asb = as + buf * BM * PA;
        float* wsb = ws + buf * BKG * PB;
#pragma unroll
        for (int i = 0; i < 2; i++) {
            int G = i * 256 + t;
            int row = G >> 2, gg = G & 3;
            bool ok = (m0 + row) < M;
            const float* gp = ok ? (X + (size_t)(m0 + row) * K + k0 + gg * 4) : X;
            uint32_t sa = (uint32_t)__cvta_generic_to_shared(asb + row * PA + gg * 4);
            int sz = ok ? 16 : 0;
            asm volatile("cp.async.cg.shared.global [%0], [%1], 16, %2;\n"
                         :: "r"(sa), "l"(gp), "r"(sz));
        }
        {
            int kr = t >> 4, gn = t & 15;
            const float* gp = W + (size_t)(k0 + kr) * 64 + gn * 4;
            uint32_t sa = (uint32_t)__cvta_generic_to_shared(wsb + kr * PB + gn * 4);
            asm volatile("cp.async.cg.shared.global [%0], [%1], 16;\n"
                         :: "r"(sa), "l"(gp));
        }
    };

    load_stage(0, 0);
    asm volatile("cp.async.commit_group;\n");

    const int NIT = K / BKG;
    for (int it = 0; it < NIT; it++) {
        if (it + 1 < NIT) load_stage((it + 1) & 1, (it + 1) * BKG);
        asm volatile("cp.async.commit_group;\n");
        asm volatile("cp.async.wait_group 1;\n");
        __syncthreads();

        const float* asb = as + (it & 1) * BM * PA;
        const float* wsb = ws + (it & 1) * BKG * PB;

#pragma unroll
        for (int ks = 0; ks < BKG; ks += 8) {
            uint32_t a[2][4], b[4][2];
#pragma unroll
            for (int mt = 0; mt < 2; mt++) {
                int r = wm * 32 + mt * 16 + g;
                a[mt][0] = cvt_tf32(asb[r * PA + ks + tig]);
                a[mt][1] = cvt_tf32(asb[(r + 8) * PA + ks + tig]);
                a[mt][2] = cvt_tf32(asb[r * PA + ks + tig + 4]);
                a[mt][3] = cvt_tf32(asb[(r + 8) * PA + ks + tig + 4]);
            }
#pragma unroll
            for (int nt = 0; nt < 4; nt++) {
                int n = wn * 32 + nt * 8 + g;
                b[nt][0] = cvt_tf32(wsb[(ks + tig) * PB + n]);
                b[nt][1] = cvt_tf32(wsb[(ks + tig + 4) * PB + n]);
            }
#pragma unroll
            for (int mt = 0; mt < 2; mt++)
#pragma unroll
                for (int nt = 0; nt < 4; nt++) {
                    asm volatile(
                        "mma.sync.aligned.m16n8k8.row.col.f32.tf32.tf32.f32 "
                        "{%0,%1,%2,%3}, {%4,%5,%6,%7}, {%8,%9}, {%0,%1,%2,%3};"
                        : "+f"(c[mt][nt][0]), "+f"(c[mt][nt][1]),
                          "+f"(c[mt][nt][2]), "+f"(c[mt][nt][3])
                        : "r"(a[mt][0]), "r"(a[mt][1]), "r"(a[mt][2]), "r"(a[mt][3]),
                          "r"(b[nt][0]), "r"(b[nt][1]));
                }
        }
        __syncthreads();
    }

#pragma unroll
    for (int mt = 0; mt < 2; mt++) {
        int rbase = m0 + wm * 32 + mt * 16 + g;
#pragma unroll
        for (int half = 0; half < 2; half++) {
            int row = rbase + half * 8;
            if (row < M) {
#pragma unroll
                for (int nt = 0; nt < 4; nt++) {
                    float2 v;
                    v.x = c[mt][nt][half * 2 + 0];
                    v.y = c[mt][nt][half * 2 + 1];
                    *(float2*)(h + (size_t)row * 64 + wn * 32 + nt * 8 + 2 * tig) = v;
                }
            }
        }
    }
}

// ---------------------------------------------------------------------------
// Fused aggregate (warp per node, unscaled h input):
//   out[i] = act(dinv[i] * (h[i]*dinv[i] + sum_e h[col[e]]*dinv[col[e]]) + b)
// ---------------------------------------------------------------------------
template <bool RELU>
__global__ void __launch_bounds__(256)
k_agg(const int* __restrict__ rowptr, const int* __restrict__ col,
      const float* __restrict__ h, const float* __restrict__ dinv,
      const float* __restrict__ bias, float* __restrict__ out, int n) {
    int w = (blockIdx.x * blockDim.x + threadIdx.x) >> 5;
    int lane = threadIdx.x & 31;
    if (w >= n) return;

    float di = __ldg(&dinv[w]);
    const float* hrow = h + (size_t)w * 64;
    float a0 = __ldg(&hrow[lane]) * di;
    float a1 = __ldg(&hrow[lane + 32]) * di;

    int beg = __ldg(&rowptr[w]);
    int end = __ldg(&rowptr[w + 1]);

    for (int e0 = beg; e0 < end; e0 += 16) {
        int idx = e0 + (lane & 15);
        int cs = (idx < end) ? __ldg(&col[idx]) : -1;
#pragma unroll
        for (int j = 0; j < 16; j++) {
            int s = __shfl_sync(0xffffffffu, cs, j);
            if (s >= 0) {
                float ds = __ldg(&dinv[s]);
                const float* hr = h + (size_t)s * 64;
                a0 = fmaf(__ldg(&hr[lane]),      ds, a0);
                a1 = fmaf(__ldg(&hr[lane + 32]), ds, a1);
            }
        }
    }

    float v0 = di * a0 + __ldg(&bias[lane]);
    float v1 = di * a1 + __ldg(&bias[lane + 32]);
    if (RELU) { v0 = fmaxf(v0, 0.0f); v1 = fmaxf(v1, 0.0f); }
    out[(size_t)w * 64 + lane]      = v0;
    out[(size_t)w * 64 + lane + 32] = v1;
}

// ---------------------------------------------------------------------------
// Launch
// ---------------------------------------------------------------------------
extern "C" void kernel_launch(void* const* d_in, const int* in_sizes, int n_in,
                              void* d_out, int out_size) {
    const float* x  = (const float*)d_in[0];
    const int*   ei = (const int*)d_in[1];
    const float* W1 = (const float*)d_in[2];
    const float* b1 = (const float*)d_in[3];
    const float* W2 = (const float*)d_in[4];
    const float* b2 = (const float*)d_in[5];

    const int E = in_sizes[1] / 2;
    const int M = out_size / HID;
    const int* src = ei;
    const int* dst = ei + E;

    float *dinv, *bufA, *bufB;
    int *cnt, *rowptr, *cursor, *col, *bsum, *boff;
    cudaGetSymbolAddress((void**)&dinv,   g_dinv);
    cudaGetSymbolAddress((void**)&cnt,    g_cnt);
    cudaGetSymbolAddress((void**)&rowptr, g_rowptr);
    cudaGetSymbolAddress((void**)&cursor, g_cursor);
    cudaGetSymbolAddress((void**)&col,    g_col);
    cudaGetSymbolAddress((void**)&bsum,   g_bsum);
    cudaGetSymbolAddress((void**)&boff,   g_boff);
    cudaGetSymbolAddress((void**)&bufA,   g_bufA);
    cudaGetSymbolAddress((void**)&bufB,   g_bufB);
    float* out = (float*)d_out;

    const int gblk = (M + BM - 1) / BM;
    const int ablk = (M * 32 + 255) / 256;
    const int nb   = (M + SCAN_B - 1) / SCAN_B;

    // 1. CSR prefix (coalesced multi-block scan)
    k_zero<<<(M + 255) / 256, 256>>>(cnt, M);
    k_count<<<592, 256>>>(dst, cnt, E);
    k_s1<<<nb, SCAN_B>>>(cnt, bsum, M);
    // 2. GEMM1 at launch #4 (profiled): h1 = x@W1 -> bufA
    k_gemm<IN_DIM><<<gblk, 256>>>(x, W1, bufA, M);
    k_s2<<<1, SCAN_B>>>(bsum, boff, rowptr, nb, M);
    k_s3<<<nb, SCAN_B>>>(cnt, boff, rowptr, cursor, dinv, M);
    k_fill<<<592, 256>>>(src, dst, cursor, col, E);

    // 3. agg1 (+bias1, ReLU) -> bufB
    k_agg<true><<<ablk, 256>>>(rowptr, col, bufA, dinv, b1, bufB, M);

    // 4. GEMM2 -> bufA ; agg2 (+bias2) -> out
    k_gemm<HID><<<gblk, 256>>>(bufB, W2, bufA, M);
    k_agg<false><<<ablk, 256>>>(rowptr, col, bufA, dinv, b2, out, M);
}